// round 13
// baseline (speedup 1.0000x reference)
#include <cuda_runtime.h>
#include <cuda_fp16.h>
#include <stdint.h>
#include <math.h>

// Problem constants
#define D        256
#define NE       8192
#define T_TOTAL  32768
#define BETA     0.25f

// GEMM tiling (fp16 single pass, K=256)
#define BM       128           // tokens per CTA
#define BN       128           // codes per chunk
#define STG_KS   4             // ksteps per B stage
#define NCHUNK   64            // NE / BN
#define NIT      256           // NCHUNK * 4 stages
#define THREADS  256

#define SA_BYTES (8 * 16 * 32 * 16)    // [mg][ks][lane] uint4 = 65536
#define SB_BYTES (16 * 4 * 32 * 8)     // [hl][ksl][lane] uint2 = 16384

#define ESCALE   16384.0f              // 2^14: emb prescale (exact)
#define DESCALE  0.0001220703125f      // 2^-13 (normal in fp16, exact pow2)

// Scratch (device globals; no runtime allocation)
__device__ uint4  g_za[2048 * 512];                 // 16 MB: A frags
__device__ uint2  g_eb[1024 * 512];                 // 4 MB:  B frags
__device__ __half g_m2[(size_t)T_TOTAL * NE];       // 512 MB: approx 2*dot
__device__ float  g_mx[T_TOTAL];                    // per-token row max (stored domain)
__device__ float  g_z2[T_TOTAL];
__device__ float  g_az[T_TOTAL];
__device__ int    g_idx[T_TOTAL];
__device__ float  g_partial[1024];

// ---------------------------------------------------------------------------
__device__ __forceinline__ uint32_t smem_u32(const void* p) {
    uint32_t a;
    asm("{ .reg .u64 t; cvta.to.shared.u64 t, %1; cvt.u32.u64 %0, t; }" : "=r"(a) : "l"(p));
    return a;
}
__device__ __forceinline__ void cp_async16(uint32_t dst, const void* src) {
    asm volatile("cp.async.cg.shared.global [%0], [%1], 16;" :: "r"(dst), "l"(src));
}
__device__ __forceinline__ void cp_commit() {
    asm volatile("cp.async.commit_group;" ::: "memory");
}
__device__ __forceinline__ void cp_wait1() {
    asm volatile("cp.async.wait_group 1;" ::: "memory");
}
__device__ __forceinline__ void cp_wait0() {
    asm volatile("cp.async.wait_group 0;" ::: "memory");
}
// fp16-accumulate HMMA: half the accumulator RF traffic of the f32 form
__device__ __forceinline__ void mma_f16h(uint32_t& c0, uint32_t& c1,
                                         const uint4 a, uint32_t b0, uint32_t b1) {
    asm volatile(
        "mma.sync.aligned.m16n8k16.row.col.f16.f16.f16.f16 "
        "{%0,%1}, {%2,%3,%4,%5}, {%6,%7}, {%0,%1};"
        : "+r"(c0), "+r"(c1)
        : "r"(a.x), "r"(a.y), "r"(a.z), "r"(a.w), "r"(b0), "r"(b1));
}
__device__ __forceinline__ float ulp_of(float x) {
    return __uint_as_float(((__float_as_uint(x) >> 23) - 23) << 23);
}
__device__ __forceinline__ uint32_t pack_h2(float a, float b) {
    __half2 h = __floats2half2_rn(a, b);
    return *reinterpret_cast<uint32_t*>(&h);
}

// ---------------------------------------------------------------------------
// Prep A: z -> fp16 mma-A fragments (m16n8k16). [g][ks][lane] uint4.
// ---------------------------------------------------------------------------
__global__ void vq_prep_z(const float* __restrict__ z) {
    int g = blockIdx.x;                 // 0..2047
    int tid = threadIdx.x;
    uint4* out = g_za + (size_t)g * 512;
#pragma unroll
    for (int it = 0; it < 2; it++) {
        int idx = tid + it * THREADS;   // 0..511
        int ks = idx >> 5, l = idx & 31;
        int gid = l >> 2, tig = l & 3;
        int kb = ks * 16 + 2 * tig;
        const float* r0 = z + (size_t)(g * 16 + gid) * D;
        const float* r1 = r0 + 8 * D;
        float2 p0 = *(const float2*)(r0 + kb);
        float2 p1 = *(const float2*)(r1 + kb);
        float2 p2 = *(const float2*)(r0 + kb + 8);
        float2 p3 = *(const float2*)(r1 + kb + 8);
        uint4 v;
        v.x = pack_h2(p0.x, p0.y);
        v.y = pack_h2(p1.x, p1.y);
        v.z = pack_h2(p2.x, p2.y);
        v.w = pack_h2(p3.x, p3.y);
        out[idx] = v;
    }
}

// ---------------------------------------------------------------------------
// Prep B: emb * 2^14 -> fp16 mma-B fragments. [h][ks][lane] uint2.
// ---------------------------------------------------------------------------
__global__ void vq_prep_e(const float* __restrict__ emb) {
    int h = blockIdx.x;                 // 0..1023
    int tid = threadIdx.x;
    uint2* out = g_eb + (size_t)h * 512;
#pragma unroll
    for (int it = 0; it < 2; it++) {
        int idx = tid + it * THREADS;
        int ks = idx >> 5, l = idx & 31;
        int gid = l >> 2, tig = l & 3;
        int kb = ks * 16 + 2 * tig;
        const float* r = emb + (size_t)(h * 8 + gid) * D;
        float2 p0 = *(const float2*)(r + kb);
        float2 p1 = *(const float2*)(r + kb + 8);
        uint2 v;
        v.x = pack_h2(p0.x * ESCALE, p0.y * ESCALE);
        v.y = pack_h2(p1.x * ESCALE, p1.y * ESCALE);
        out[idx] = v;
    }
}

// ---------------------------------------------------------------------------
// Token norms: z2 = sum z^2, az = sum |z|. One warp per token.
// ---------------------------------------------------------------------------
__global__ void vq_norms(const float* __restrict__ z) {
    int t = (blockIdx.x * blockDim.x + threadIdx.x) >> 5;
    int lane = threadIdx.x & 31;
    if (t >= T_TOTAL) return;
    const float* row = z + (size_t)t * D;
    float s2 = 0.f, sa = 0.f;
#pragma unroll
    for (int i = 0; i < D / 32; i++) {
        float v = row[lane + 32 * i];
        s2 = fmaf(v, v, s2);
        sa += fabsf(v);
    }
#pragma unroll
    for (int o = 16; o; o >>= 1) {
        s2 += __shfl_xor_sync(0xffffffffu, s2, o);
        sa += __shfl_xor_sync(0xffffffffu, sa, o);
    }
    if (lane == 0) { g_z2[t] = s2; g_az[t] = sa; }
}

// ---------------------------------------------------------------------------
// GEMM: fp16 mma with FP16 accumulators. A smem-resident, B double-buffered.
// Epilogue stores fp16 m2 AND folds a running per-token max -> g_mx.
// ---------------------------------------------------------------------------
extern __shared__ char smem_raw[];

__global__ void __launch_bounds__(THREADS, 2)
vq_gemm(void) {
    const int tid  = threadIdx.x;
    const int lane = tid & 31;
    const int wid  = tid >> 5;
    const int wm   = wid >> 1;          // 0..3
    const int wn   = wid & 1;           // 0..1
    const int gid  = lane >> 2;
    const int tig  = lane & 3;
    const int t0   = blockIdx.x * BM;

    char* sA = smem_raw;
    char* sB[2] = { smem_raw + SA_BYTES, smem_raw + SA_BYTES + SB_BYTES };
    uint32_t sAu = smem_u32(sA);
    uint32_t sBu[2] = { smem_u32(sB[0]), smem_u32(sB[1]) };

    // load A (64 KB) once
    {
        const uint4* gA = g_za + (size_t)blockIdx.x * 8 * 512;
#pragma unroll
        for (int j = 0; j < 16; j++) {
            int f = tid + j * THREADS;  // 0..4095
            cp_async16(sAu + f * 16, gA + f);
        }
    }
    const char* gE = (const char*)g_eb;
    auto fillB = [&](int buf, int it) {
        int chunk = it >> 2, s = it & 3;
#pragma unroll
        for (int j = 0; j < 4; j++) {
            int f = tid + j * THREADS;         // 0..1023 (16B units)
            int hl = f >> 6, rem = f & 63;
            int ksl = rem >> 4, w = rem & 15;
            const char* src = gE + ((size_t)(chunk * 16 + hl) * 4096
                                    + (s * STG_KS + ksl) * 256 + w * 16);
            cp_async16(sBu[buf] + (hl * STG_KS + ksl) * 256 + w * 16, src);
        }
    };
    fillB(0, 0); cp_commit();
    fillB(1, 1); cp_commit();

    uint32_t acc0[2][8], acc1[2][8];    // fp16x2 accumulators (rows gid / gid+8)
    const __half2 dsc2 = __floats2half2_rn(DESCALE, DESCALE);
    __half2 rmx[2][2];                  // running max per (im, h), stored domain
#pragma unroll
    for (int im = 0; im < 2; im++)
#pragma unroll
        for (int h = 0; h < 2; h++)
            rmx[im][h] = __floats2half2_rn(-65504.f, -65504.f);

    for (int it = 0; it < NIT; it++) {
        const int chunk = it >> 2, s = it & 3, buf = it & 1;
        if (it + 1 < NIT) cp_wait1(); else cp_wait0();
        __syncthreads();

        if (s == 0) {
#pragma unroll
            for (int im = 0; im < 2; im++)
#pragma unroll
                for (int in = 0; in < 8; in++) { acc0[im][in] = 0u; acc1[im][in] = 0u; }
        }

        const char* pB = sB[buf];
#pragma unroll
        for (int ksl = 0; ksl < STG_KS; ksl++) {
            int ks = s * STG_KS + ksl;
            uint4 a[2];
#pragma unroll
            for (int im = 0; im < 2; im++) {
                int mg = wm * 2 + im;
                a[im] = *(const uint4*)(sA + (((mg * 16 + ks) * 32 + lane) << 4));
            }
#pragma unroll
            for (int in = 0; in < 8; in++) {
                int hl = wn * 8 + in;
                uint2 b = *(const uint2*)(pB + (((hl * STG_KS + ksl) * 32 + lane) << 3));
#pragma unroll
                for (int im = 0; im < 2; im++)
                    mma_f16h(acc0[im][in], acc1[im][in], a[im], b.x, b.y);
            }
        }
        __syncthreads();
        if (it + 2 < NIT) { fillB(buf, it + 2); cp_commit(); }

        if (s == 3) {
            // epilogue: descale (exact pow2) -> store fp16, fold row max
#pragma unroll
            for (int im = 0; im < 2; im++) {
                int tr0 = t0 + (wm * 2 + im) * 16 + gid;
                __half* d0 = g_m2 + (size_t)tr0 * NE + chunk * 128 + wn * 64 + 2 * tig;
                __half* d1 = d0 + (size_t)8 * NE;
#pragma unroll
                for (int in = 0; in < 8; in++) {
                    __half2 v0 = __hmul2(*(const __half2*)&acc0[im][in], dsc2);
                    __half2 v1 = __hmul2(*(const __half2*)&acc1[im][in], dsc2);
                    rmx[im][0] = __hmax2(rmx[im][0], v0);
                    rmx[im][1] = __hmax2(rmx[im][1], v1);
                    *(__half2*)(d0 + in * 8) = v0;
                    *(__half2*)(d1 + in * 8) = v1;
                }
            }
        }
    }

    // per-token max: reduce over tig lanes, then across the 2 wn warps via smem
    __syncthreads();
    float* smx = (float*)smem_raw;       // [2][128]
#pragma unroll
    for (int im = 0; im < 2; im++)
#pragma unroll
        for (int h = 0; h < 2; h++) {
            float m = fmaxf(__half2float(__low2half(rmx[im][h])),
                            __half2float(__high2half(rmx[im][h])));
#pragma unroll
            for (int o = 1; o <= 2; o <<= 1)
                m = fmaxf(m, __shfl_xor_sync(0xffffffffu, m, o));
            if (tig == 0) {
                int trl = (wm * 2 + im) * 16 + h * 8 + gid;
                smx[wn * 128 + trl] = m;
            }
        }
    __syncthreads();
    for (int trl = tid; trl < 128; trl += THREADS)
        g_mx[t0 + trl] = fmaxf(smx[trl], smx[128 + trl]);
}

// ---------------------------------------------------------------------------
// Pick: warp per token, SINGLE pass (g_mx known). Hard-bound candidate set,
// exact sequential-fmaf recompute, lowest-index tie-break.
// ---------------------------------------------------------------------------
#define CAP 128
__global__ void __launch_bounds__(256, 1)
vq_pick(const float* __restrict__ z, const float* __restrict__ emb,
        float* __restrict__ out_idx_f) {
    __shared__ float sz[8][D];
    __shared__ int   slist[8][CAP];
    __shared__ int   scnt[8];
    const int w    = threadIdx.x >> 5;
    const int lane = threadIdx.x & 31;
    const int t    = blockIdx.x * 8 + w;

    {
        float4* dst = (float4*)sz[w];
        const float4* src = (const float4*)(z + (size_t)t * D);
        dst[lane] = src[lane];
        dst[lane + 32] = src[lane + 32];
    }
    if (lane == 0) scnt[w] = 0;
    __syncwarp();

    const float z2 = g_z2[t];
    const float az = g_az[t];
    // hard bound: input conversion + fp16-accumulate (16 roundings, 2x safety)
    // + fp16 store + slack
    const float eps_in  = 0.001953125f * 1.2207031e-4f * az;   // 2^-9 emax az
    const float eps_acc = 0.0625f      * 1.2207031e-4f * az;   // 2^-4 emax az
    const float M   = ulp_of(z2) + 2.0f * (eps_in + eps_acc) + 4.0e-5f;
    const float thr = g_mx[t] - M;

    const uint4* r4 = (const uint4*)(g_m2 + (size_t)t * NE);
#pragma unroll 4
    for (int j = 0; j < 32; j++) {
        uint4 v = r4[j * 32 + lane];
        const __half2* hp = (const __half2*)&v;
        int ebase = (j * 32 + lane) * 8;
#pragma unroll
        for (int p = 0; p < 4; p++) {
            float2 f = __half22float2(hp[p]);
            if (f.x >= thr) {
                int pos = atomicAdd(&scnt[w], 1);
                if (pos < CAP) slist[w][pos] = ebase + p * 2;
            }
            if (f.y >= thr) {
                int pos = atomicAdd(&scnt[w], 1);
                if (pos < CAP) slist[w][pos] = ebase + p * 2 + 1;
            }
        }
    }
    __syncwarp();
    int cnt = scnt[w];

    float bv = 3.0e38f;
    int   bi = 0x7fffffff;
    const float* zz = sz[w];

    if (cnt <= CAP) {
        for (int base = 0; base < cnt; base += 32) {
            int ci = base + lane;
            float dv = 3.0e38f;
            int   e  = 0x7fffffff;
            if (ci < cnt) {
                e = slist[w][ci];
                const float* er = emb + (size_t)e * D;
                float d = 0.f;
#pragma unroll 8
                for (int k = 0; k < D; k++) d = fmaf(zz[k], er[k], d);
                dv = __fadd_rn(z2, -__fmul_rn(2.f, d));
            }
            if (dv < bv || (dv == bv && e < bi)) { bv = dv; bi = e; }
        }
    } else {
        // overflow fallback: exact full scan (codes ascending per lane)
        for (int c = 0; c < 256; c++) {
            int e = lane * 256 + c;
            const float* er = emb + (size_t)e * D;
            float d = 0.f;
#pragma unroll 8
            for (int k = 0; k < D; k++) d = fmaf(zz[k], er[k], d);
            float dv = __fadd_rn(z2, -__fmul_rn(2.f, d));
            if (dv < bv) { bv = dv; bi = e; }
        }
    }
#pragma unroll
    for (int o = 16; o; o >>= 1) {
        float ov = __shfl_xor_sync(0xffffffffu, bv, o);
        int   oi = __shfl_xor_sync(0xffffffffu, bi, o);
        if (ov < bv || (ov == bv && oi < bi)) { bv = ov; bi = oi; }
    }
    if (lane == 0) {
        g_idx[t] = bi;
        out_idx_f[t] = (float)bi;
    }
}

// ---------------------------------------------------------------------------
// Gather: z_q = emb[idx]; STE-exact output z + fl(z_q - z); loss partials.
// ---------------------------------------------------------------------------
__global__ void vq_gather_kernel(const float* __restrict__ z,
                                 const float* __restrict__ emb,
                                 float* __restrict__ out_zq) {
    int gwarp = (blockIdx.x * blockDim.x + threadIdx.x) >> 5;
    int lane  = threadIdx.x & 31;
    float s = 0.f;
#pragma unroll
    for (int j = 0; j < 4; j++) {
        int t = gwarp * 4 + j;
        int e = g_idx[t];
        const float* er = emb + (size_t)e * D;
        const float* zr = z   + (size_t)t * D;
        float*       o  = out_zq + (size_t)t * D;
#pragma unroll
        for (int i = 0; i < D / 32; i++) {
            int c = lane + 32 * i;
            float q  = er[c];
            float zc = zr[c];
            float d  = __fadd_rn(q, -zc);
            s = fmaf(d, d, s);
            o[c] = __fadd_rn(zc, d);
        }
    }
#pragma unroll
    for (int o2 = 16; o2; o2 >>= 1) s += __shfl_xor_sync(0xffffffffu, s, o2);
    __shared__ float ws[8];
    if (lane == 0) ws[threadIdx.x >> 5] = s;
    __syncthreads();
    if (threadIdx.x == 0) {
        float tsum = 0.f;
#pragma unroll
        for (int i = 0; i < 8; i++) tsum += ws[i];
        g_partial[blockIdx.x] = tsum;
    }
}

__global__ void vq_finalize_kernel(float* __restrict__ out_loss) {
    int tid = threadIdx.x;
    double s = 0.0;
#pragma unroll
    for (int i = 0; i < 4; i++) s += (double)g_partial[tid + 256 * i];
#pragma unroll
    for (int o = 16; o; o >>= 1) s += __shfl_xor_sync(0xffffffffu, s, o);
    __shared__ double ws[8];
    if ((tid & 31) == 0) ws[tid >> 5] = s;
    __syncthreads();
    if (tid == 0) {
        double t = 0.0;
#pragma unroll
        for (int i = 0; i < 8; i++) t += ws[i];
        *out_loss = (float)((1.0 + (double)BETA) * t / (double)((size_t)T_TOTAL * D));
    }
}

// ---------------------------------------------------------------------------
extern "C" void kernel_launch(void* const* d_in, const int* in_sizes, int n_in,
                              void* d_out, int out_size) {
    const float* z   = (const float*)d_in[0];   // [8,4096,256] fp32
    const float* emb = (const float*)d_in[1];   // [8192,256] fp32
    float* out       = (float*)d_out;
    float* out_zq    = out;
    float* out_loss  = out + (size_t)T_TOTAL * D;
    float* out_idx   = out + (size_t)T_TOTAL * D + 1;

    vq_prep_z<<<2048, THREADS>>>(z);
    vq_prep_e<<<1024, THREADS>>>(emb);
    vq_norms<<<T_TOTAL / 8, 256>>>(z);

    size_t smem_bytes = SA_BYTES + 2 * SB_BYTES;   // 98304
    cudaFuncSetAttribute(vq_gemm,
                         cudaFuncAttributeMaxDynamicSharedMemorySize,
                         (int)smem_bytes);
    vq_gemm<<<T_TOTAL / BM, THREADS, smem_bytes>>>();

    vq_pick<<<T_TOTAL / 8, 256>>>(z, emb, out_idx);
    vq_gather_kernel<<<1024, 256>>>(z, emb, out_zq);
    vq_finalize_kernel<<<1, 256>>>(out_loss);
}

// round 14
// speedup vs baseline: 115.3557x; 115.3557x over previous
#include <cuda_runtime.h>
#include <cuda_fp16.h>
#include <stdint.h>
#include <math.h>

// Problem constants
#define D        256
#define NE       8192
#define T_TOTAL  32768
#define BETA     0.25f

// GEMM tiling (fp16 inputs, fp32 accum, K=256)
#define BM       128           // tokens per CTA
#define BN       128           // codes per chunk
#define STG_KS   4             // ksteps per B stage
#define NCHUNK   64            // NE / BN
#define NIT      256           // NCHUNK * 4 stages
#define THREADS  256

#define SA_BYTES (8 * 16 * 32 * 16)    // 65536
#define SB_BYTES (16 * 4 * 32 * 8)     // 16384

#define ESCALE   16384.0f              // 2^14 emb prescale (exact)
#define DESCALE  0.0001220703125f      // 2^-13

// Scratch (device globals; no runtime allocation)
__device__ uint4  g_za[2048 * 512];                 // 16 MB: A frags
__device__ uint2  g_eb[1024 * 512];                 // 4 MB:  B frags
__device__ __half g_m2[(size_t)T_TOTAL * NE];       // 512 MB: approx 2*dot
__device__ float  g_mx[T_TOTAL];                    // per-token row max
__device__ float  g_z2[T_TOTAL];
__device__ float  g_az[T_TOTAL];
__device__ int    g_idx[T_TOTAL];
__device__ float  g_partial[1024];

// ---------------------------------------------------------------------------
__device__ __forceinline__ uint32_t smem_u32(const void* p) {
    uint32_t a;
    asm("{ .reg .u64 t; cvta.to.shared.u64 t, %1; cvt.u32.u64 %0, t; }" : "=r"(a) : "l"(p));
    return a;
}
__device__ __forceinline__ void cp_async16(uint32_t dst, const void* src) {
    asm volatile("cp.async.cg.shared.global [%0], [%1], 16;" :: "r"(dst), "l"(src));
}
__device__ __forceinline__ void cp_commit() {
    asm volatile("cp.async.commit_group;" ::: "memory");
}
__device__ __forceinline__ void cp_wait1() {
    asm volatile("cp.async.wait_group 1;" ::: "memory");
}
__device__ __forceinline__ void cp_wait0() {
    asm volatile("cp.async.wait_group 0;" ::: "memory");
}
__device__ __forceinline__ void mma_f16(float* c, const uint4 a, uint32_t b0, uint32_t b1) {
    asm volatile(
        "mma.sync.aligned.m16n8k16.row.col.f32.f16.f16.f32 "
        "{%0,%1,%2,%3}, {%4,%5,%6,%7}, {%8,%9}, {%0,%1,%2,%3};"
        : "+f"(c[0]), "+f"(c[1]), "+f"(c[2]), "+f"(c[3])
        : "r"(a.x), "r"(a.y), "r"(a.z), "r"(a.w), "r"(b0), "r"(b1));
}
__device__ __forceinline__ float ulp_of(float x) {
    return __uint_as_float(((__float_as_uint(x) >> 23) - 23) << 23);
}
__device__ __forceinline__ uint32_t pack_h2(float a, float b) {
    __half2 h = __floats2half2_rn(a, b);
    return *reinterpret_cast<uint32_t*>(&h);
}

// ---------------------------------------------------------------------------
// Prep A: z -> fp16 mma-A fragments (m16n8k16). [g][ks][lane] uint4.
// ---------------------------------------------------------------------------
__global__ void vq_prep_z(const float* __restrict__ z) {
    int g = blockIdx.x;                 // 0..2047
    int tid = threadIdx.x;
    uint4* out = g_za + (size_t)g * 512;
#pragma unroll
    for (int it = 0; it < 2; it++) {
        int idx = tid + it * THREADS;   // 0..511
        int ks = idx >> 5, l = idx & 31;
        int gid = l >> 2, tig = l & 3;
        int kb = ks * 16 + 2 * tig;
        const float* r0 = z + (size_t)(g * 16 + gid) * D;
        const float* r1 = r0 + 8 * D;
        float2 p0 = *(const float2*)(r0 + kb);
        float2 p1 = *(const float2*)(r1 + kb);
        float2 p2 = *(const float2*)(r0 + kb + 8);
        float2 p3 = *(const float2*)(r1 + kb + 8);
        uint4 v;
        v.x = pack_h2(p0.x, p0.y);
        v.y = pack_h2(p1.x, p1.y);
        v.z = pack_h2(p2.x, p2.y);
        v.w = pack_h2(p3.x, p3.y);
        out[idx] = v;
    }
}

// ---------------------------------------------------------------------------
// Prep B: emb * 2^14 -> fp16 mma-B fragments. [h][ks][lane] uint2.
// ---------------------------------------------------------------------------
__global__ void vq_prep_e(const float* __restrict__ emb) {
    int h = blockIdx.x;                 // 0..1023
    int tid = threadIdx.x;
    uint2* out = g_eb + (size_t)h * 512;
#pragma unroll
    for (int it = 0; it < 2; it++) {
        int idx = tid + it * THREADS;
        int ks = idx >> 5, l = idx & 31;
        int gid = l >> 2, tig = l & 3;
        int kb = ks * 16 + 2 * tig;
        const float* r = emb + (size_t)(h * 8 + gid) * D;
        float2 p0 = *(const float2*)(r + kb);
        float2 p1 = *(const float2*)(r + kb + 8);
        uint2 v;
        v.x = pack_h2(p0.x * ESCALE, p0.y * ESCALE);
        v.y = pack_h2(p1.x * ESCALE, p1.y * ESCALE);
        out[idx] = v;
    }
}

// ---------------------------------------------------------------------------
// Token norms: z2 = sum z^2, az = sum |z|. One warp per token.
// ---------------------------------------------------------------------------
__global__ void vq_norms(const float* __restrict__ z) {
    int t = (blockIdx.x * blockDim.x + threadIdx.x) >> 5;
    int lane = threadIdx.x & 31;
    if (t >= T_TOTAL) return;
    const float* row = z + (size_t)t * D;
    float s2 = 0.f, sa = 0.f;
#pragma unroll
    for (int i = 0; i < D / 32; i++) {
        float v = row[lane + 32 * i];
        s2 = fmaf(v, v, s2);
        sa += fabsf(v);
    }
#pragma unroll
    for (int o = 16; o; o >>= 1) {
        s2 += __shfl_xor_sync(0xffffffffu, s2, o);
        sa += __shfl_xor_sync(0xffffffffu, sa, o);
    }
    if (lane == 0) { g_z2[t] = s2; g_az[t] = sa; }
}

// ---------------------------------------------------------------------------
// GEMM: fp16 mma with FP32 accumulators (validated margins). A smem-resident,
// B double-buffered. Epilogue stores fp16 m2 AND folds per-token max -> g_mx.
// ---------------------------------------------------------------------------
extern __shared__ char smem_raw[];

__global__ void __launch_bounds__(THREADS, 2)
vq_gemm(void) {
    const int tid  = threadIdx.x;
    const int lane = tid & 31;
    const int wid  = tid >> 5;
    const int wm   = wid >> 1;          // 0..3
    const int wn   = wid & 1;           // 0..1
    const int gid  = lane >> 2;
    const int tig  = lane & 3;
    const int t0   = blockIdx.x * BM;

    char* sA = smem_raw;
    char* sB[2] = { smem_raw + SA_BYTES, smem_raw + SA_BYTES + SB_BYTES };
    uint32_t sAu = smem_u32(sA);
    uint32_t sBu[2] = { smem_u32(sB[0]), smem_u32(sB[1]) };

    // load A (64 KB) once
    {
        const uint4* gA = g_za + (size_t)blockIdx.x * 8 * 512;
#pragma unroll
        for (int j = 0; j < 16; j++) {
            int f = tid + j * THREADS;  // 0..4095
            cp_async16(sAu + f * 16, gA + f);
        }
    }
    const char* gE = (const char*)g_eb;
    auto fillB = [&](int buf, int it) {
        int chunk = it >> 2, s = it & 3;
#pragma unroll
        for (int j = 0; j < 4; j++) {
            int f = tid + j * THREADS;         // 0..1023 (16B units)
            int hl = f >> 6, rem = f & 63;
            int ksl = rem >> 4, w = rem & 15;
            const char* src = gE + ((size_t)(chunk * 16 + hl) * 4096
                                    + (s * STG_KS + ksl) * 256 + w * 16);
            cp_async16(sBu[buf] + (hl * STG_KS + ksl) * 256 + w * 16, src);
        }
    };
    fillB(0, 0); cp_commit();
    fillB(1, 1); cp_commit();

    float acc[2][8][4];
    float rmx[2][2] = { {-3.0e38f, -3.0e38f}, {-3.0e38f, -3.0e38f} };

    for (int it = 0; it < NIT; it++) {
        const int chunk = it >> 2, s = it & 3, buf = it & 1;
        if (it + 1 < NIT) cp_wait1(); else cp_wait0();
        __syncthreads();

        if (s == 0) {
#pragma unroll
            for (int im = 0; im < 2; im++)
#pragma unroll
                for (int in = 0; in < 8; in++)
#pragma unroll
                    for (int q = 0; q < 4; q++) acc[im][in][q] = 0.f;
        }

        const char* pB = sB[buf];
#pragma unroll
        for (int ksl = 0; ksl < STG_KS; ksl++) {
            int ks = s * STG_KS + ksl;
            uint4 a[2];
#pragma unroll
            for (int im = 0; im < 2; im++) {
                int mg = wm * 2 + im;
                a[im] = *(const uint4*)(sA + (((mg * 16 + ks) * 32 + lane) << 4));
            }
#pragma unroll
            for (int in = 0; in < 8; in++) {
                int hl = wn * 8 + in;
                uint2 b = *(const uint2*)(pB + (((hl * STG_KS + ksl) * 32 + lane) << 3));
#pragma unroll
                for (int im = 0; im < 2; im++)
                    mma_f16(acc[im][in], a[im], b.x, b.y);
            }
        }
        __syncthreads();
        if (it + 2 < NIT) { fillB(buf, it + 2); cp_commit(); }

        if (s == 3) {
            // epilogue: store m2 = acc * 2^-13 as fp16; fold fp32 running max
#pragma unroll
            for (int im = 0; im < 2; im++)
#pragma unroll
                for (int h = 0; h < 2; h++) {
                    int trow = t0 + (wm * 2 + im) * 16 + h * 8 + gid;
                    __half* dst = g_m2 + (size_t)trow * NE + chunk * 128 + wn * 64 + 2 * tig;
#pragma unroll
                    for (int in = 0; in < 8; in++) {
                        float2 f2;
                        f2.x = acc[im][in][h * 2 + 0] * DESCALE;
                        f2.y = acc[im][in][h * 2 + 1] * DESCALE;
                        rmx[im][h] = fmaxf(rmx[im][h], fmaxf(f2.x, f2.y));
                        *(__half2*)(dst + in * 8) = __float22half2_rn(f2);
                    }
                }
        }
    }

    // per-token max: reduce over tig lanes, then across the 2 wn warps
    __syncthreads();
    float* smx = (float*)smem_raw;       // [2][128]
#pragma unroll
    for (int im = 0; im < 2; im++)
#pragma unroll
        for (int h = 0; h < 2; h++) {
            float m = rmx[im][h];
#pragma unroll
            for (int o = 1; o <= 2; o <<= 1)
                m = fmaxf(m, __shfl_xor_sync(0xffffffffu, m, o));
            if (tig == 0) {
                int trl = (wm * 2 + im) * 16 + h * 8 + gid;
                smx[wn * 128 + trl] = m;
            }
        }
    __syncthreads();
    for (int trl = tid; trl < 128; trl += THREADS)
        g_mx[t0 + trl] = fmaxf(smx[trl], smx[128 + trl]);
}

// ---------------------------------------------------------------------------
// Pick: warp per token, SINGLE pass (g_mx known). Hard-bound candidate set
// (fp32-acc margins, validated in round 10), exact sequential-fmaf recompute,
// lowest-index tie-break.
// ---------------------------------------------------------------------------
#define CAP 64
__global__ void __launch_bounds__(256, 1)
vq_pick(const float* __restrict__ z, const float* __restrict__ emb,
        float* __restrict__ out_idx_f) {
    __shared__ float sz[8][D];
    __shared__ int   slist[8][CAP];
    __shared__ int   scnt[8];
    const int w    = threadIdx.x >> 5;
    const int lane = threadIdx.x & 31;
    const int t    = blockIdx.x * 8 + w;

    {
        float4* dst = (float4*)sz[w];
        const float4* src = (const float4*)(z + (size_t)t * D);
        dst[lane] = src[lane];
        dst[lane + 32] = src[lane + 32];
    }
    if (lane == 0) scnt[w] = 0;
    __syncwarp();

    const float z2 = g_z2[t];
    const float az = g_az[t];
    // hard bound (fp32 accum): conversion + fp16 store + g_mx-vs-stored gap + slack
    const float eps_a = 0.001953125f * 1.2207031e-4f * az + 8.2e-6f;
    const float M   = ulp_of(z2) + 2.0f * eps_a + 1.7e-5f;
    const float thr = g_mx[t] - M;

    const uint4* r4 = (const uint4*)(g_m2 + (size_t)t * NE);
#pragma unroll 4
    for (int j = 0; j < 32; j++) {
        uint4 v = r4[j * 32 + lane];
        const __half2* hp = (const __half2*)&v;
        int ebase = (j * 32 + lane) * 8;
#pragma unroll
        for (int p = 0; p < 4; p++) {
            float2 f = __half22float2(hp[p]);
            if (f.x >= thr) {
                int pos = atomicAdd(&scnt[w], 1);
                if (pos < CAP) slist[w][pos] = ebase + p * 2;
            }
            if (f.y >= thr) {
                int pos = atomicAdd(&scnt[w], 1);
                if (pos < CAP) slist[w][pos] = ebase + p * 2 + 1;
            }
        }
    }
    __syncwarp();
    int cnt = scnt[w];

    float bv = 3.0e38f;
    int   bi = 0x7fffffff;
    const float* zz = sz[w];

    if (cnt <= CAP) {
        for (int base = 0; base < cnt; base += 32) {
            int ci = base + lane;
            float dv = 3.0e38f;
            int   e  = 0x7fffffff;
            if (ci < cnt) {
                e = slist[w][ci];
                const float* er = emb + (size_t)e * D;
                float d = 0.f;
#pragma unroll 8
                for (int k = 0; k < D; k++) d = fmaf(zz[k], er[k], d);
                dv = __fadd_rn(z2, -__fmul_rn(2.f, d));
            }
            if (dv < bv || (dv == bv && e < bi)) { bv = dv; bi = e; }
        }
    } else {
        // overflow fallback: exact full scan (codes ascending per lane)
        for (int c = 0; c < 256; c++) {
            int e = lane * 256 + c;
            const float* er = emb + (size_t)e * D;
            float d = 0.f;
#pragma unroll 8
            for (int k = 0; k < D; k++) d = fmaf(zz[k], er[k], d);
            float dv = __fadd_rn(z2, -__fmul_rn(2.f, d));
            if (dv < bv) { bv = dv; bi = e; }
        }
    }
#pragma unroll
    for (int o = 16; o; o >>= 1) {
        float ov = __shfl_xor_sync(0xffffffffu, bv, o);
        int   oi = __shfl_xor_sync(0xffffffffu, bi, o);
        if (ov < bv || (ov == bv && oi < bi)) { bv = ov; bi = oi; }
    }
    if (lane == 0) {
        g_idx[t] = bi;
        out_idx_f[t] = (float)bi;
    }
}

// ---------------------------------------------------------------------------
// Gather: z_q = emb[idx]; STE-exact output z + fl(z_q - z); loss partials.
// ---------------------------------------------------------------------------
__global__ void vq_gather_kernel(const float* __restrict__ z,
                                 const float* __restrict__ emb,
                                 float* __restrict__ out_zq) {
    int gwarp = (blockIdx.x * blockDim.x + threadIdx.x) >> 5;
    int lane  = threadIdx.x & 31;
    float s = 0.f;
#pragma unroll
    for (int j = 0; j < 4; j++) {
        int t = gwarp * 4 + j;
        int e = g_idx[t];
        const float* er = emb + (size_t)e * D;
        const float* zr = z   + (size_t)t * D;
        float*       o  = out_zq + (size_t)t * D;
#pragma unroll
        for (int i = 0; i < D / 32; i++) {
            int c = lane + 32 * i;
            float q  = er[c];
            float zc = zr[c];
            float d  = __fadd_rn(q, -zc);
            s = fmaf(d, d, s);
            o[c] = __fadd_rn(zc, d);
        }
    }
#pragma unroll
    for (int o2 = 16; o2; o2 >>= 1) s += __shfl_xor_sync(0xffffffffu, s, o2);
    __shared__ float ws[8];
    if (lane == 0) ws[threadIdx.x >> 5] = s;
    __syncthreads();
    if (threadIdx.x == 0) {
        float tsum = 0.f;
#pragma unroll
        for (int i = 0; i < 8; i++) tsum += ws[i];
        g_partial[blockIdx.x] = tsum;
    }
}

__global__ void vq_finalize_kernel(float* __restrict__ out_loss) {
    int tid = threadIdx.x;
    double s = 0.0;
#pragma unroll
    for (int i = 0; i < 4; i++) s += (double)g_partial[tid + 256 * i];
#pragma unroll
    for (int o = 16; o; o >>= 1) s += __shfl_xor_sync(0xffffffffu, s, o);
    __shared__ double ws[8];
    if ((tid & 31) == 0) ws[tid >> 5] = s;
    __syncthreads();
    if (tid == 0) {
        double t = 0.0;
#pragma unroll
        for (int i = 0; i < 8; i++) t += ws[i];
        *out_loss = (float)((1.0 + (double)BETA) * t / (double)((size_t)T_TOTAL * D));
    }
}

// ---------------------------------------------------------------------------
extern "C" void kernel_launch(void* const* d_in, const int* in_sizes, int n_in,
                              void* d_out, int out_size) {
    const float* z   = (const float*)d_in[0];   // [8,4096,256] fp32
    const float* emb = (const float*)d_in[1];   // [8192,256] fp32
    float* out       = (float*)d_out;
    float* out_zq    = out;
    float* out_loss  = out + (size_t)T_TOTAL * D;
    float* out_idx   = out + (size_t)T_TOTAL * D + 1;

    vq_prep_z<<<2048, THREADS>>>(z);
    vq_prep_e<<<1024, THREADS>>>(emb);
    vq_norms<<<T_TOTAL / 8, 256>>>(z);

    size_t smem_bytes = SA_BYTES + 2 * SB_BYTES;   // 98304
    cudaFuncSetAttribute(vq_gemm,
                         cudaFuncAttributeMaxDynamicSharedMemorySize,
                         (int)smem_bytes);
    vq_gemm<<<T_TOTAL / BM, THREADS, smem_bytes>>>();

    vq_pick<<<T_TOTAL / 8, 256>>>(z, emb, out_idx);
    vq_gather_kernel<<<1024, 256>>>(z, emb, out_zq);
    vq_finalize_kernel<<<1, 256>>>(out_loss);
}